// round 15
// baseline (speedup 1.0000x reference)
#include <cuda_runtime.h>
#include <cuda_bf16.h>
#include <cuda_fp16.h>
#include <cstdint>
#include <cstddef>

#define D_IN   96
#define D_OUT  256
#define MAXN   50000

// -------- scratch (device globals; no allocation allowed) --------
__device__ __align__(16) float g_agg[(size_t)MAXN * D_IN];    // 19.2 MB
// W fp16 pair-layout: entry(kc,pp,n,j) = half2(W[k0][n], W[k0+1][n]),
// k0 = 16*kc + 2*pp + 8*j.  uint32 index = ((kc*4+pp)*256 + n)*2 + j.
__device__ __align__(16) uint32_t g_w0ph[12288];              // W0: 96x256 f16
__device__ __align__(16) uint32_t g_w1ph[32768];              // W1: 256x256 f16
__device__ __align__(16) float g_scale[D_OUT];
__device__ __align__(16) float g_shift[D_OUT];

// ---------------- helpers ----------------
__device__ __forceinline__ uint32_t smem_u32(const void* p) {
    uint32_t a;
    asm("{ .reg .u64 t; cvta.to.shared.u64 t, %1; cvt.u32.u64 %0, t; }"
        : "=r"(a) : "l"(p));
    return a;
}
__device__ __forceinline__ uint32_t packh2(float lo, float hi) {
    __half2 h = __floats2half2_rn(lo, hi);   // .x = lo, .y = hi
    return *reinterpret_cast<uint32_t*>(&h);
}

__device__ __forceinline__ void mma_f16(float d[4], const uint32_t a[4],
                                        const uint32_t b[2], const float c[4]) {
    asm volatile(
        "mma.sync.aligned.m16n8k16.row.col.f32.f16.f16.f32 "
        "{%0,%1,%2,%3}, {%4,%5,%6,%7}, {%8,%9}, {%10,%11,%12,%13};"
        : "=f"(d[0]), "=f"(d[1]), "=f"(d[2]), "=f"(d[3])
        : "r"(a[0]), "r"(a[1]), "r"(a[2]), "r"(a[3]),
          "r"(b[0]), "r"(b[1]),
          "f"(c[0]), "f"(c[1]), "f"(c[2]), "f"(c[3]));
}

__device__ __forceinline__ void cp_async16(uint32_t dst, const void* src, uint32_t sz) {
    asm volatile("cp.async.cg.shared.global [%0], [%1], 16, %2;"
                 :: "r"(dst), "l"(src), "r"(sz) : "memory");
}
__device__ __forceinline__ void cp_commit() {
    asm volatile("cp.async.commit_group;" ::: "memory");
}

// -------- kernel 1: agg = eps * x --------
__global__ void init_agg_kernel(const float* __restrict__ x,
                                const float* __restrict__ eps, int n4) {
    int i = blockIdx.x * blockDim.x + threadIdx.x;
    if (i >= n4) return;
    float e = eps[0];
    float4 xv = reinterpret_cast<const float4*>(x)[i];
    reinterpret_cast<float4*>(g_agg)[i] =
        make_float4(e * xv.x, e * xv.y, e * xv.z, e * xv.w);
}

// -------- kernel 2: BN params + fp16 pair-packed weights --------
__global__ void prep_kernel(const float* __restrict__ gamma,
                            const float* __restrict__ beta,
                            const float* __restrict__ mean,
                            const float* __restrict__ var,
                            const float* __restrict__ W0,
                            const float* __restrict__ W1) {
    int t = blockIdx.x * blockDim.x + threadIdx.x;
    if (t < D_OUT) {
        float s = gamma[t] * rsqrtf(var[t] + 1e-3f);
        g_scale[t] = s;
        g_shift[t] = beta[t] - mean[t] * s;
    }
    if (t < 32768) {
        int j  = t & 1;
        int n  = (t >> 1) & 255;
        int pp = (t >> 9) & 3;
        int kc = t >> 11;
        int k0 = kc * 16 + pp * 2 + j * 8;
        g_w1ph[t] = packh2(W1[(size_t)k0 * D_OUT + n],
                           W1[(size_t)(k0 + 1) * D_OUT + n]);
    }
    if (t < 12288) {
        int j  = t & 1;
        int n  = (t >> 1) & 255;
        int pp = (t >> 9) & 3;
        int kc = t >> 11;
        int k0 = kc * 16 + pp * 2 + j * 8;
        g_w0ph[t] = packh2(W0[(size_t)k0 * D_OUT + n],
                           W0[(size_t)(k0 + 1) * D_OUT + n]);
    }
}

// -------- vectorized global reduction (sm_90+) --------
__device__ __forceinline__ void red_add_v4(float* addr, float4 v) {
    asm volatile("red.global.add.v4.f32 [%0], {%1, %2, %3, %4};"
                 :: "l"(addr), "f"(v.x), "f"(v.y), "f"(v.z), "f"(v.w)
                 : "memory");
}

// -------- kernel 3: edge scatter  agg[dst] += vals * x[src] --------
__global__ void edge_scatter_kernel(const float* __restrict__ x,
                                    const int* __restrict__ src,
                                    const int* __restrict__ dst,
                                    const float* __restrict__ vals, int E) {
    int idx = blockIdx.x * blockDim.x + threadIdx.x;
    int e = idx / 24;
    if (e >= E) return;
    int c = idx - e * 24;
    int s = __ldg(src + e);
    int d = __ldg(dst + e);
    float v = __ldg(vals + e);
    float4 xv = __ldg(reinterpret_cast<const float4*>(x + (size_t)s * D_IN) + c);
    red_add_v4(g_agg + (size_t)d * D_IN + c * 4,
               make_float4(v * xv.x, v * xv.y, v * xv.z, v * xv.w));
}

// =================== kernel 4: fused GEMM1 + BN/ReLU + GEMM2 (fp16 mma) ========
// 64 rows x 256 cols, 8 warps, warp tile 32x64 (2M x 4N of m16n8k16).
// 3-STAGE cp.async pipeline: copy for step s+2 issued inside step s -> two full
// steps of gmem-latency lead; ONE __syncthreads per step (3 buffers make the
// write target (s+2)%3 == (s-1)%3, whose reads drained at this step's barrier).
#define ROWS  64
#define SH    132
#define H_BYTES (ROWS * SH * 4)              // 33792
#define SA    24
#define A_BYTES (ROWS * SA * 4)              // 6144
#define WROW_B 2080
#define W_BYTES (4 * WROW_B)                 // 8320
#define STG_BYTES (A_BYTES + W_BYTES)        // 14464
#define ARENA_BYTES (3 * STG_BYTES)          // 43392
#define FUSED_SMEM (H_BYTES + ARENA_BYTES)   // 77184

__global__ __launch_bounds__(256, 2) void fused_gemm_kernel(
    const float* __restrict__ A, const uint32_t* __restrict__ W0p,
    const uint32_t* __restrict__ W1p, float* __restrict__ out, int M)
{
    extern __shared__ char smem[];
    uint32_t* hs = reinterpret_cast<uint32_t*>(smem);
    char* arena = smem + H_BYTES;
    const uint32_t sb_ar = smem_u32(arena);

    const int tid  = threadIdx.x;
    const int lane = tid & 31;
    const int warp = tid >> 5;
    const int warpM = warp & 1;        // 2 x 32 rows
    const int warpN = warp >> 1;       // 4 x 64 cols
    const int gid  = lane >> 2;
    const int ctig = lane & 3;
    const int crow0 = blockIdx.x * ROWS;

    float acc[2][8][4];
    #pragma unroll
    for (int mt = 0; mt < 2; mt++)
        #pragma unroll
        for (int nt = 0; nt < 8; nt++)
            #pragma unroll
            for (int i = 0; i < 4; i++) acc[mt][nt][i] = 0.f;

    // W chunk copy: 512 x 16B (4 pair-rows x 128)
    auto copy_w = [&](const uint32_t* Wp, int kc, uint32_t wb) {
        #pragma unroll
        for (int j = 0; j < 2; j++) {
            int id = tid + j * 256;
            int pp = id >> 7;            // 0..3
            int n2 = id & 127;
            cp_async16(wb + (uint32_t)(pp * WROW_B + n2 * 16),
                       Wp + ((size_t)(kc * 4 + pp) * D_OUT + n2 * 2) * 2, 16u);
        }
    };
    auto copy_a = [&](int s, uint32_t ab) {
        int row = tid >> 2, ch = tid & 3;
        int gr = crow0 + row;
        int grc = gr < M ? gr : (M - 1);
        cp_async16(ab + (uint32_t)(row * SA + ch * 4) * 4,
                   A + (size_t)grc * D_IN + (s << 4) + ch * 4, gr < M ? 16u : 0u);
    };
    auto copy_p1 = [&](int s) {
        const uint32_t ab = sb_ar + (s % 3) * STG_BYTES;
        copy_a(s, ab);
        copy_w(W0p, s, ab + A_BYTES);
    };

    copy_p1(0); cp_commit();
    copy_p1(1); cp_commit();

    const int c2 = 2 * ctig;

    // ---------------- phase 1: h = f16(relu(BN(agg @ W0))), K=96 ----------------
    for (int s = 0; s < 6; s++) {
        asm volatile("cp.async.wait_group 1;" ::: "memory");
        __syncthreads();
        if (s + 2 < 6) copy_p1(s + 2);
        cp_commit();

        const char* stg = arena + (s % 3) * STG_BYTES;
        const float* as = reinterpret_cast<const float*>(stg);
        const char* wsb = stg + A_BYTES;

        uint32_t af[2][4];
        #pragma unroll
        for (int mt = 0; mt < 2; mt++) {
            int m0 = warpM * 32 + mt * 16 + gid;
            float2 x0 = *reinterpret_cast<const float2*>(&as[m0 * SA + c2]);
            float2 x1 = *reinterpret_cast<const float2*>(&as[(m0 + 8) * SA + c2]);
            float2 x2 = *reinterpret_cast<const float2*>(&as[m0 * SA + c2 + 8]);
            float2 x3 = *reinterpret_cast<const float2*>(&as[(m0 + 8) * SA + c2 + 8]);
            af[mt][0] = packh2(x0.x, x0.y);
            af[mt][1] = packh2(x1.x, x1.y);
            af[mt][2] = packh2(x2.x, x2.y);
            af[mt][3] = packh2(x3.x, x3.y);
        }
        const char* wrow = wsb + ctig * WROW_B;
        uint32_t bf[8][2];
        #pragma unroll
        for (int nt = 0; nt < 8; nt++) {
            int n0 = warpN * 64 + nt * 8 + gid;
            float2 wv = *reinterpret_cast<const float2*>(wrow + n0 * 8);
            bf[nt][0] = __float_as_uint(wv.x);
            bf[nt][1] = __float_as_uint(wv.y);
        }
        #pragma unroll
        for (int mt = 0; mt < 2; mt++)
            #pragma unroll
            for (int nt = 0; nt < 8; nt++)
                mma_f16(acc[mt][nt], af[mt], bf[nt], acc[mt][nt]);
    }

    // phase-1 epilogue: BN + ReLU -> h (half2 k-pairs)
    #pragma unroll
    for (int nt = 0; nt < 8; nt++) {
        int col = warpN * 64 + nt * 8 + c2;
        int kpc = col >> 1;
        float sc0 = g_scale[col], sc1 = g_scale[col + 1];
        float sh0 = g_shift[col], sh1 = g_shift[col + 1];
        #pragma unroll
        for (int mt = 0; mt < 2; mt++) {
            int r = warpM * 32 + mt * 16 + gid;
            float v0 = fmaxf(fmaf(acc[mt][nt][0], sc0, sh0), 0.f);
            float v1 = fmaxf(fmaf(acc[mt][nt][1], sc1, sh1), 0.f);
            float v2 = fmaxf(fmaf(acc[mt][nt][2], sc0, sh0), 0.f);
            float v3 = fmaxf(fmaf(acc[mt][nt][3], sc1, sh1), 0.f);
            hs[r * SH + kpc]       = packh2(v0, v1);
            hs[(r + 8) * SH + kpc] = packh2(v2, v3);
        }
    }

    // ---------------- phase 2: out = h @ W1, K=256 ----------------
    #pragma unroll
    for (int mt = 0; mt < 2; mt++)
        #pragma unroll
        for (int nt = 0; nt < 8; nt++)
            #pragma unroll
            for (int i = 0; i < 4; i++) acc[mt][nt][i] = 0.f;

    __syncthreads();            // h visible; all phase-1 arena reads drained
    copy_w(W1p, 0, sb_ar + A_BYTES); cp_commit();
    copy_w(W1p, 1, sb_ar + STG_BYTES + A_BYTES); cp_commit();

    for (int s = 0; s < 16; s++) {
        asm volatile("cp.async.wait_group 1;" ::: "memory");
        __syncthreads();
        if (s + 2 < 16)
            copy_w(W1p, s + 2, sb_ar + ((s + 2) % 3) * STG_BYTES + A_BYTES);
        cp_commit();

        const char* wsb = arena + (s % 3) * STG_BYTES + A_BYTES;
        const int kpb = s * 8 + ctig;

        uint32_t af[2][4];
        #pragma unroll
        for (int mt = 0; mt < 2; mt++) {
            int m0 = warpM * 32 + mt * 16 + gid;
            af[mt][0] = hs[m0 * SH + kpb];
            af[mt][1] = hs[(m0 + 8) * SH + kpb];
            af[mt][2] = hs[m0 * SH + kpb + 4];
            af[mt][3] = hs[(m0 + 8) * SH + kpb + 4];
        }
        const char* wrow = wsb + ctig * WROW_B;
        uint32_t bf[8][2];
        #pragma unroll
        for (int nt = 0; nt < 8; nt++) {
            int n0 = warpN * 64 + nt * 8 + gid;
            float2 wv = *reinterpret_cast<const float2*>(wrow + n0 * 8);
            bf[nt][0] = __float_as_uint(wv.x);
            bf[nt][1] = __float_as_uint(wv.y);
        }
        #pragma unroll
        for (int mt = 0; mt < 2; mt++)
            #pragma unroll
            for (int nt = 0; nt < 8; nt++)
                mma_f16(acc[mt][nt], af[mt], bf[nt], acc[mt][nt]);
    }

    // phase-2 epilogue: store out (fp32)
    #pragma unroll
    for (int nt = 0; nt < 8; nt++) {
        int col = warpN * 64 + nt * 8 + c2;
        #pragma unroll
        for (int mt = 0; mt < 2; mt++) {
            int row = crow0 + warpM * 32 + mt * 16 + gid;
            if (row < M)
                *reinterpret_cast<float2*>(out + (size_t)row * D_OUT + col) =
                    make_float2(acc[mt][nt][0], acc[mt][nt][1]);
            if (row + 8 < M)
                *reinterpret_cast<float2*>(out + (size_t)(row + 8) * D_OUT + col) =
                    make_float2(acc[mt][nt][2], acc[mt][nt][3]);
        }
    }
}

extern "C" void kernel_launch(void* const* d_in, const int* in_sizes, int n_in,
                              void* d_out, int out_size) {
    const float* x        = (const float*)d_in[0];
    const int*   adj_src  = (const int*)  d_in[1];
    const int*   adj_dst  = (const int*)  d_in[2];
    const float* adj_vals = (const float*)d_in[3];
    const float* eps      = (const float*)d_in[4];
    const float* W0       = (const float*)d_in[5];
    const float* W1       = (const float*)d_in[6];
    const float* gamma    = (const float*)d_in[7];
    const float* beta     = (const float*)d_in[8];
    const float* bn_mean  = (const float*)d_in[9];
    const float* bn_var   = (const float*)d_in[10];
    float* out = (float*)d_out;

    int N = in_sizes[0] / D_IN;
    int E = in_sizes[1];

    void* p;
    cudaGetSymbolAddress(&p, g_agg);    float*    agg = (float*)p;
    cudaGetSymbolAddress(&p, g_w0ph);   uint32_t* w0p = (uint32_t*)p;
    cudaGetSymbolAddress(&p, g_w1ph);   uint32_t* w1p = (uint32_t*)p;

    cudaFuncSetAttribute(fused_gemm_kernel,
                         cudaFuncAttributeMaxDynamicSharedMemorySize, FUSED_SMEM);

    // launch 1) agg = eps * x
    int n4 = N * (D_IN / 4);
    init_agg_kernel<<<(n4 + 255) / 256, 256>>>(x, eps, n4);

    // launch 2) BN params + fp16 pair-packed weights
    prep_kernel<<<(32768 + 255) / 256, 256>>>(gamma, beta, bn_mean, bn_var, W0, W1);

    // launch 3) scatter edges into agg (vectorized L2 reductions)
    int work = E * (D_IN / 4);
    edge_scatter_kernel<<<(work + 255) / 256, 256>>>(x, adj_src, adj_dst, adj_vals, E);

    // launch 4) fused GEMM1 + BN/ReLU + GEMM2 (fp16 tensor)  (profiled slot)
    fused_gemm_kernel<<<(N + ROWS - 1) / ROWS, 256, FUSED_SMEM>>>(agg, w0p, w1p, out, N);
}

// round 16
// speedup vs baseline: 1.0054x; 1.0054x over previous
#include <cuda_runtime.h>
#include <cuda_bf16.h>
#include <cuda_fp16.h>
#include <cstdint>
#include <cstddef>

#define D_IN   96
#define D_OUT  256
#define MAXN   50000

// -------- scratch (device globals; no allocation allowed) --------
__device__ __align__(16) float g_agg[(size_t)MAXN * D_IN];    // 19.2 MB
// W fp16 pair-layout: entry(kc,pp,n,j) = half2(W[k0][n], W[k0+1][n]),
// k0 = 16*kc + 2*pp + 8*j.  uint32 index = ((kc*4+pp)*256 + n)*2 + j.
__device__ __align__(16) uint32_t g_w0ph[12288];              // W0: 96x256 f16
__device__ __align__(16) uint32_t g_w1ph[32768];              // W1: 256x256 f16
__device__ __align__(16) float g_scale[D_OUT];
__device__ __align__(16) float g_shift[D_OUT];

// ---------------- helpers ----------------
__device__ __forceinline__ uint32_t smem_u32(const void* p) {
    uint32_t a;
    asm("{ .reg .u64 t; cvta.to.shared.u64 t, %1; cvt.u32.u64 %0, t; }"
        : "=r"(a) : "l"(p));
    return a;
}
__device__ __forceinline__ uint32_t packh2(float lo, float hi) {
    __half2 h = __floats2half2_rn(lo, hi);   // .x = lo, .y = hi
    return *reinterpret_cast<uint32_t*>(&h);
}

__device__ __forceinline__ void mma_f16(float d[4], const uint32_t a[4],
                                        const uint32_t b[2], const float c[4]) {
    asm volatile(
        "mma.sync.aligned.m16n8k16.row.col.f32.f16.f16.f32 "
        "{%0,%1,%2,%3}, {%4,%5,%6,%7}, {%8,%9}, {%10,%11,%12,%13};"
        : "=f"(d[0]), "=f"(d[1]), "=f"(d[2]), "=f"(d[3])
        : "r"(a[0]), "r"(a[1]), "r"(a[2]), "r"(a[3]),
          "r"(b[0]), "r"(b[1]),
          "f"(c[0]), "f"(c[1]), "f"(c[2]), "f"(c[3]));
}

__device__ __forceinline__ void cp_async16(uint32_t dst, const void* src, uint32_t sz) {
    asm volatile("cp.async.cg.shared.global [%0], [%1], 16, %2;"
                 :: "r"(dst), "l"(src), "r"(sz) : "memory");
}
__device__ __forceinline__ void cp_commit() {
    asm volatile("cp.async.commit_group;" ::: "memory");
}

// -------- kernel 1: agg = eps * x --------
__global__ void init_agg_kernel(const float* __restrict__ x,
                                const float* __restrict__ eps, int n4) {
    int i = blockIdx.x * blockDim.x + threadIdx.x;
    if (i >= n4) return;
    float e = eps[0];
    float4 xv = reinterpret_cast<const float4*>(x)[i];
    reinterpret_cast<float4*>(g_agg)[i] =
        make_float4(e * xv.x, e * xv.y, e * xv.z, e * xv.w);
}

// -------- kernel 2: BN params + fp16 pair-packed weights --------
__global__ void prep_kernel(const float* __restrict__ gamma,
                            const float* __restrict__ beta,
                            const float* __restrict__ mean,
                            const float* __restrict__ var,
                            const float* __restrict__ W0,
                            const float* __restrict__ W1) {
    int t = blockIdx.x * blockDim.x + threadIdx.x;
    if (t < D_OUT) {
        float s = gamma[t] * rsqrtf(var[t] + 1e-3f);
        g_scale[t] = s;
        g_shift[t] = beta[t] - mean[t] * s;
    }
    if (t < 32768) {
        int j  = t & 1;
        int n  = (t >> 1) & 255;
        int pp = (t >> 9) & 3;
        int kc = t >> 11;
        int k0 = kc * 16 + pp * 2 + j * 8;
        g_w1ph[t] = packh2(W1[(size_t)k0 * D_OUT + n],
                           W1[(size_t)(k0 + 1) * D_OUT + n]);
    }
    if (t < 12288) {
        int j  = t & 1;
        int n  = (t >> 1) & 255;
        int pp = (t >> 9) & 3;
        int kc = t >> 11;
        int k0 = kc * 16 + pp * 2 + j * 8;
        g_w0ph[t] = packh2(W0[(size_t)k0 * D_OUT + n],
                           W0[(size_t)(k0 + 1) * D_OUT + n]);
    }
}

// -------- vectorized global reduction (sm_90+) --------
__device__ __forceinline__ void red_add_v4(float* addr, float4 v) {
    asm volatile("red.global.add.v4.f32 [%0], {%1, %2, %3, %4};"
                 :: "l"(addr), "f"(v.x), "f"(v.y), "f"(v.z), "f"(v.w)
                 : "memory");
}

// -------- kernel 3: edge scatter  agg[dst] += vals * x[src] --------
__global__ void edge_scatter_kernel(const float* __restrict__ x,
                                    const int* __restrict__ src,
                                    const int* __restrict__ dst,
                                    const float* __restrict__ vals, int E) {
    int idx = blockIdx.x * blockDim.x + threadIdx.x;
    int e = idx / 24;
    if (e >= E) return;
    int c = idx - e * 24;
    int s = __ldg(src + e);
    int d = __ldg(dst + e);
    float v = __ldg(vals + e);
    float4 xv = __ldg(reinterpret_cast<const float4*>(x + (size_t)s * D_IN) + c);
    red_add_v4(g_agg + (size_t)d * D_IN + c * 4,
               make_float4(v * xv.x, v * xv.y, v * xv.z, v * xv.w));
}

// =================== kernel 4: fused GEMM1 + BN/ReLU + GEMM2 (fp16 mma) ========
// 64 rows x 256 cols, 4 warps, warp tile 64x64 (4M x 8N of m16n8k16).
// 128 B smem traffic per MMA (vs 192 at 32x64). 3-stage cp.async pipeline,
// one __syncthreads per step. 2 CTAs/SM (77184 B smem), 256 regs/thread avail.
#define ROWS  64
#define SH    132
#define H_BYTES (ROWS * SH * 4)              // 33792
#define SA    24
#define A_BYTES (ROWS * SA * 4)              // 6144
#define WROW_B 2080
#define W_BYTES (4 * WROW_B)                 // 8320
#define STG_BYTES (A_BYTES + W_BYTES)        // 14464
#define ARENA_BYTES (3 * STG_BYTES)          // 43392
#define FUSED_SMEM (H_BYTES + ARENA_BYTES)   // 77184

__global__ __launch_bounds__(128, 2) void fused_gemm_kernel(
    const float* __restrict__ A, const uint32_t* __restrict__ W0p,
    const uint32_t* __restrict__ W1p, float* __restrict__ out, int M)
{
    extern __shared__ char smem[];
    uint32_t* hs = reinterpret_cast<uint32_t*>(smem);
    char* arena = smem + H_BYTES;
    const uint32_t sb_ar = smem_u32(arena);

    const int tid  = threadIdx.x;
    const int lane = tid & 31;
    const int warp = tid >> 5;         // 0..3 -> 64-col slice each
    const int gid  = lane >> 2;
    const int ctig = lane & 3;
    const int crow0 = blockIdx.x * ROWS;

    float acc[4][8][4];
    #pragma unroll
    for (int mt = 0; mt < 4; mt++)
        #pragma unroll
        for (int nt = 0; nt < 8; nt++)
            #pragma unroll
            for (int i = 0; i < 4; i++) acc[mt][nt][i] = 0.f;

    // W chunk copy: 512 x 16B over 128 threads (4 each)
    auto copy_w = [&](const uint32_t* Wp, int kc, uint32_t wb) {
        #pragma unroll
        for (int j = 0; j < 4; j++) {
            int id = tid + j * 128;
            int pp = id >> 7;            // 0..3
            int n2 = id & 127;
            cp_async16(wb + (uint32_t)(pp * WROW_B + n2 * 16),
                       Wp + ((size_t)(kc * 4 + pp) * D_OUT + n2 * 2) * 2, 16u);
        }
    };
    auto copy_a = [&](int s, uint32_t ab) {
        #pragma unroll
        for (int j = 0; j < 2; j++) {
            int id = tid + j * 128;
            int row = id >> 2, ch = id & 3;
            int gr = crow0 + row;
            int grc = gr < M ? gr : (M - 1);
            cp_async16(ab + (uint32_t)(row * SA + ch * 4) * 4,
                       A + (size_t)grc * D_IN + (s << 4) + ch * 4, gr < M ? 16u : 0u);
        }
    };
    auto copy_p1 = [&](int s) {
        const uint32_t ab = sb_ar + (s % 3) * STG_BYTES;
        copy_a(s, ab);
        copy_w(W0p, s, ab + A_BYTES);
    };

    copy_p1(0); cp_commit();
    copy_p1(1); cp_commit();

    const int c2 = 2 * ctig;

    // ---------------- phase 1: h = f16(relu(BN(agg @ W0))), K=96 ----------------
    for (int s = 0; s < 6; s++) {
        asm volatile("cp.async.wait_group 1;" ::: "memory");
        __syncthreads();
        if (s + 2 < 6) copy_p1(s + 2);
        cp_commit();

        const char* stg = arena + (s % 3) * STG_BYTES;
        const float* as = reinterpret_cast<const float*>(stg);
        const char* wsb = stg + A_BYTES;

        uint32_t af[4][4];
        #pragma unroll
        for (int mt = 0; mt < 4; mt++) {
            int m0 = mt * 16 + gid;
            float2 x0 = *reinterpret_cast<const float2*>(&as[m0 * SA + c2]);
            float2 x1 = *reinterpret_cast<const float2*>(&as[(m0 + 8) * SA + c2]);
            float2 x2 = *reinterpret_cast<const float2*>(&as[m0 * SA + c2 + 8]);
            float2 x3 = *reinterpret_cast<const float2*>(&as[(m0 + 8) * SA + c2 + 8]);
            af[mt][0] = packh2(x0.x, x0.y);
            af[mt][1] = packh2(x1.x, x1.y);
            af[mt][2] = packh2(x2.x, x2.y);
            af[mt][3] = packh2(x3.x, x3.y);
        }
        const char* wrow = wsb + ctig * WROW_B;
        uint32_t bf[8][2];
        #pragma unroll
        for (int nt = 0; nt < 8; nt++) {
            int n0 = warp * 64 + nt * 8 + gid;
            float2 wv = *reinterpret_cast<const float2*>(wrow + n0 * 8);
            bf[nt][0] = __float_as_uint(wv.x);
            bf[nt][1] = __float_as_uint(wv.y);
        }
        #pragma unroll
        for (int mt = 0; mt < 4; mt++)
            #pragma unroll
            for (int nt = 0; nt < 8; nt++)
                mma_f16(acc[mt][nt], af[mt], bf[nt], acc[mt][nt]);
    }

    // phase-1 epilogue: BN + ReLU -> h (half2 k-pairs)
    #pragma unroll
    for (int nt = 0; nt < 8; nt++) {
        int col = warp * 64 + nt * 8 + c2;
        int kpc = col >> 1;
        float sc0 = g_scale[col], sc1 = g_scale[col + 1];
        float sh0 = g_shift[col], sh1 = g_shift[col + 1];
        #pragma unroll
        for (int mt = 0; mt < 4; mt++) {
            int r = mt * 16 + gid;
            float v0 = fmaxf(fmaf(acc[mt][nt][0], sc0, sh0), 0.f);
            float v1 = fmaxf(fmaf(acc[mt][nt][1], sc1, sh1), 0.f);
            float v2 = fmaxf(fmaf(acc[mt][nt][2], sc0, sh0), 0.f);
            float v3 = fmaxf(fmaf(acc[mt][nt][3], sc1, sh1), 0.f);
            hs[r * SH + kpc]       = packh2(v0, v1);
            hs[(r + 8) * SH + kpc] = packh2(v2, v3);
        }
    }

    // ---------------- phase 2: out = h @ W1, K=256 ----------------
    #pragma unroll
    for (int mt = 0; mt < 4; mt++)
        #pragma unroll
        for (int nt = 0; nt < 8; nt++)
            #pragma unroll
            for (int i = 0; i < 4; i++) acc[mt][nt][i] = 0.f;

    __syncthreads();            // h visible; all phase-1 arena reads drained
    copy_w(W1p, 0, sb_ar + A_BYTES); cp_commit();
    copy_w(W1p, 1, sb_ar + STG_BYTES + A_BYTES); cp_commit();

    for (int s = 0; s < 16; s++) {
        asm volatile("cp.async.wait_group 1;" ::: "memory");
        __syncthreads();
        if (s + 2 < 16)
            copy_w(W1p, s + 2, sb_ar + ((s + 2) % 3) * STG_BYTES + A_BYTES);
        cp_commit();

        const char* wsb = arena + (s % 3) * STG_BYTES + A_BYTES;
        const int kpb = s * 8 + ctig;

        uint32_t af[4][4];
        #pragma unroll
        for (int mt = 0; mt < 4; mt++) {
            int m0 = mt * 16 + gid;
            af[mt][0] = hs[m0 * SH + kpb];
            af[mt][1] = hs[(m0 + 8) * SH + kpb];
            af[mt][2] = hs[m0 * SH + kpb + 4];
            af[mt][3] = hs[(m0 + 8) * SH + kpb + 4];
        }
        const char* wrow = wsb + ctig * WROW_B;
        uint32_t bf[8][2];
        #pragma unroll
        for (int nt = 0; nt < 8; nt++) {
            int n0 = warp * 64 + nt * 8 + gid;
            float2 wv = *reinterpret_cast<const float2*>(wrow + n0 * 8);
            bf[nt][0] = __float_as_uint(wv.x);
            bf[nt][1] = __float_as_uint(wv.y);
        }
        #pragma unroll
        for (int mt = 0; mt < 4; mt++)
            #pragma unroll
            for (int nt = 0; nt < 8; nt++)
                mma_f16(acc[mt][nt], af[mt], bf[nt], acc[mt][nt]);
    }

    // phase-2 epilogue: store out (fp32)
    #pragma unroll
    for (int nt = 0; nt < 8; nt++) {
        int col = warp * 64 + nt * 8 + c2;
        #pragma unroll
        for (int mt = 0; mt < 4; mt++) {
            int row = crow0 + mt * 16 + gid;
            if (row < M)
                *reinterpret_cast<float2*>(out + (size_t)row * D_OUT + col) =
                    make_float2(acc[mt][nt][0], acc[mt][nt][1]);
            if (row + 8 < M)
                *reinterpret_cast<float2*>(out + (size_t)(row + 8) * D_OUT + col) =
                    make_float2(acc[mt][nt][2], acc[mt][nt][3]);
        }
    }
}

extern "C" void kernel_launch(void* const* d_in, const int* in_sizes, int n_in,
                              void* d_out, int out_size) {
    const float* x        = (const float*)d_in[0];
    const int*   adj_src  = (const int*)  d_in[1];
    const int*   adj_dst  = (const int*)  d_in[2];
    const float* adj_vals = (const float*)d_in[3];
    const float* eps      = (const float*)d_in[4];
    const float* W0       = (const float*)d_in[5];
    const float* W1       = (const float*)d_in[6];
    const float* gamma    = (const float*)d_in[7];
    const float* beta     = (const float*)d_in[8];
    const float* bn_mean  = (const float*)d_in[9];
    const float* bn_var   = (const float*)d_in[10];
    float* out = (float*)d_out;

    int N = in_sizes[0] / D_IN;
    int E = in_sizes[1];

    void* p;
    cudaGetSymbolAddress(&p, g_agg);    float*    agg = (float*)p;
    cudaGetSymbolAddress(&p, g_w0ph);   uint32_t* w0p = (uint32_t*)p;
    cudaGetSymbolAddress(&p, g_w1ph);   uint32_t* w1p = (uint32_t*)p;

    cudaFuncSetAttribute(fused_gemm_kernel,
                         cudaFuncAttributeMaxDynamicSharedMemorySize, FUSED_SMEM);

    // launch 1) agg = eps * x
    int n4 = N * (D_IN / 4);
    init_agg_kernel<<<(n4 + 255) / 256, 256>>>(x, eps, n4);

    // launch 2) BN params + fp16 pair-packed weights
    prep_kernel<<<(32768 + 255) / 256, 256>>>(gamma, beta, bn_mean, bn_var, W0, W1);

    // launch 3) scatter edges into agg (vectorized L2 reductions)
    int work = E * (D_IN / 4);
    edge_scatter_kernel<<<(work + 255) / 256, 256>>>(x, adj_src, adj_dst, adj_vals, E);

    // launch 4) fused GEMM1 + BN/ReLU + GEMM2 (fp16 tensor)  (profiled slot)
    fused_gemm_kernel<<<(N + ROWS - 1) / ROWS, 128, FUSED_SMEM>>>(agg, w0p, w1p, out, N);
}